// round 11
// baseline (speedup 1.0000x reference)
#include <cuda_runtime.h>

// PerBandSoftAGC: out = x / (clip(EMA100(|x|), 1e-6)^alpha + 0.1)
// x: (32, 8, 16, 8192) fp32 -> 4096 rows of T=8192, channel kc = row % 128.
// EMA weights w_i = c*q^i (i<100), q = 1 - sigmoid(log_s), c = s/((1-q^100)+1e-8).
// Linear recurrence M[t] = q*M[t-1] + u[t], u[t] = c|x[t]| - c*q^100*|x[t-100]|.
//
// One WARP per 1024-elem segment. Macro-step = 256 elems: each lane owns 8
// consecutive floats (2x float4). Local serial scan (7 FMA) -> warp Kogge-Stone
// on the lane aggregate with ratio q^8 (5 shfl) -> recombine. Carry seeded by a
// warp-parallel 100-tap FIR. No smem, no block barriers.
// R11: force 6 CTAs/SM (occupancy/latency coverage), streaming stores.

#define T_LEN   8192
#define KC_NUM  128
#define L_FIR   100
#define SEG     1024
#define TPB     256
#define WARPS_PER_BLOCK (TPB / 32)
#define VPT     8
#define MACRO   (32 * VPT)        // 256 elems per warp macro-step
#define STEPS   (SEG / MACRO)     // 4

__global__ __launch_bounds__(TPB, 6)
void per_band_soft_agc_kernel(const float* __restrict__ x,
                              const float* __restrict__ alpha_raw,
                              const float* __restrict__ log_s,
                              float* __restrict__ out)
{
    const unsigned FULL = 0xffffffffu;
    const int gw   = blockIdx.x * WARPS_PER_BLOCK + (threadIdx.x >> 5);
    const int lane = threadIdx.x & 31;
    const int row  = gw >> 3;                 // 8 segments per row
    const int o    = (gw & 7) * SEG;
    const int kc   = row & (KC_NUM - 1);

    const float* __restrict__ xr   = x   + (size_t)row * T_LEN;
    float*       __restrict__ orow = out + (size_t)row * T_LEN;

    // ---- per-channel scalars (warp-uniform) ----
    const float ls    = log_s[kc];
    const float s     = 1.0f / (1.0f + __expf(-ls));
    const float q     = 1.0f - s;
    const float l2q   = __log2f(q);
    const float qL    = exp2f(l2q * (float)L_FIR);          // q^100
    const float c     = s / ((1.0f - qL) + 1e-8f);
    const float ncqL  = -c * qL;
    const float ar    = alpha_raw[kc];
    const float alpha = 0.5f / (1.0f + __expf(-ar));

    // hoisted powers of q (all loop-invariant)
    float qp[VPT];                                           // q^1 .. q^8
    qp[0] = q;
    #pragma unroll
    for (int j = 1; j < VPT; ++j) qp[j] = qp[j - 1] * q;
    const float r1 = qp[VPT - 1];                            // q^8
    const float r2 = r1 * r1, r4 = r2 * r2, r8 = r4 * r4, r16 = r8 * r8;
    const float q256 = r16 * r16;                            // q^256
    const float q8l  = exp2f(l2q * (float)(VPT * lane));     // q^(8*lane)
    const float q32  = exp2f(l2q * 32.0f);
    const float qlane = exp2f(l2q * (float)lane);

    // ---- seed carry = M[o-1] via warp-parallel 100-tap FIR ----
    float carry = 0.0f;
    if (o > 0) {
        const float q64 = q32 * q32;
        const float q96 = q64 * q32;
        const int   b   = o - 1 - lane;
        float t = fabsf(xr[b]);
        t = fmaf(q32, fabsf(xr[b - 32]), t);
        t = fmaf(q64, fabsf(xr[b - 64]), t);
        if (lane < 4) t = fmaf(q96, fabsf(xr[b - 96]), t);
        t *= c * qlane;
        #pragma unroll
        for (int d = 16; d > 0; d >>= 1)
            t += __shfl_xor_sync(FULL, t, d);
        carry = t;                                           // exact M[o-1]
    }

    // ---- main loop: 4 macro-steps of 256 elements ----
    #pragma unroll 2
    for (int step = 0; step < STEPS; ++step) {
        const int pb = o + step * MACRO + lane * VPT;        // 8-aligned -> 16B aligned

        float xv[VPT];
        {   // two LDG.128, coalesced
            const float4 v0 = *(const float4*)(xr + pb);
            const float4 v1 = *(const float4*)(xr + pb + 4);
            xv[0] = v0.x; xv[1] = v0.y; xv[2] = v0.z; xv[3] = v0.w;
            xv[4] = v1.x; xv[5] = v1.y; xv[6] = v1.z; xv[7] = v1.w;
        }

        float xo[VPT];
        if (pb >= L_FIR) {                                   // (pb-100) % 4 == 0 -> aligned
            const float4 v0 = *(const float4*)(xr + pb - L_FIR);
            const float4 v1 = *(const float4*)(xr + pb - L_FIR + 4);
            xo[0] = v0.x; xo[1] = v0.y; xo[2] = v0.z; xo[3] = v0.w;
            xo[4] = v1.x; xo[5] = v1.y; xo[6] = v1.z; xo[7] = v1.w;
        } else {                                             // first segment, step 0 only
            #pragma unroll
            for (int j = 0; j < VPT; ++j) {
                const int p = pb + j;
                xo[j] = (p >= L_FIR) ? xr[p - L_FIR] : 0.0f;
            }
        }

        // u_j then local inclusive weighted scan (in place)
        float a[VPT];
        a[0] = fmaf(c, fabsf(xv[0]), ncqL * fabsf(xo[0]));
        #pragma unroll
        for (int j = 1; j < VPT; ++j) {
            const float u = fmaf(c, fabsf(xv[j]), ncqL * fabsf(xo[j]));
            a[j] = fmaf(q, a[j - 1], u);
        }

        // warp inclusive scan of lane aggregates with ratio q^8
        float S = a[VPT - 1];
        { float t = __shfl_up_sync(FULL, S, 1);  if (lane >= 1)  S = fmaf(r1,  t, S); }
        { float t = __shfl_up_sync(FULL, S, 2);  if (lane >= 2)  S = fmaf(r2,  t, S); }
        { float t = __shfl_up_sync(FULL, S, 4);  if (lane >= 4)  S = fmaf(r4,  t, S); }
        { float t = __shfl_up_sync(FULL, S, 8);  if (lane >= 8)  S = fmaf(r8,  t, S); }
        { float t = __shfl_up_sync(FULL, S, 16); if (lane >= 16) S = fmaf(r16, t, S); }

        // exclusive prefix from lanes below + incoming carry
        const float Ex = __shfl_up_sync(FULL, S, 1);
        const float E  = (lane >= 1) ? Ex : 0.0f;
        const float w  = fmaf(q8l, carry, E);

        const float S31 = __shfl_sync(FULL, S, 31);
        carry = fmaf(q256, carry, S31);                      // only serial cross-step dep

        // full M, gain, divide, store (streaming: write-once data, keep L2 for lag)
        float4 r0, r1v;
        #pragma unroll
        for (int j = 0; j < VPT; ++j) {
            const float M  = fmaf(qp[j], w, a[j]);
            const float g  = __powf(fmaxf(M, 1e-6f), alpha) + 0.1f;
            const float rj = __fdividef(xv[j], g);
            if (j < 4) (&r0.x)[j] = rj; else (&r1v.x)[j - 4] = rj;
        }
        __stcs((float4*)(orow + pb),     r0);                // STG.128.CS, coalesced
        __stcs((float4*)(orow + pb + 4), r1v);
    }
}

extern "C" void kernel_launch(void* const* d_in, const int* in_sizes, int n_in,
                              void* d_out, int out_size)
{
    const float* x         = (const float*)d_in[0];
    const float* alpha_raw = (const float*)d_in[1];
    const float* log_s     = (const float*)d_in[2];
    float*       out       = (float*)d_out;

    const int rows   = in_sizes[0] / T_LEN;                 // 4096
    const int warps  = rows * (T_LEN / SEG);                // 32768
    const int blocks = warps / WARPS_PER_BLOCK;             // 4096
    per_band_soft_agc_kernel<<<blocks, TPB>>>(x, alpha_raw, log_s, out);
}

// round 13
// speedup vs baseline: 1.0074x; 1.0074x over previous
#include <cuda_runtime.h>

// PerBandSoftAGC: out = x / (clip(EMA100(|x|), 1e-6)^alpha + 0.1)
// x: (32, 8, 16, 8192) fp32 -> 4096 rows of T=8192, channel kc = row % 128.
// EMA weights w_i = c*q^i (i<100), q = 1 - sigmoid(log_s), c = s/((1-q^100)+1e-8).
// Linear recurrence M[t] = q*M[t-1] + u[t], u[t] = c|x[t]| - c*q^100*|x[t-100]|.
//
// One WARP per 1024-elem segment. Macro-step = 256 elems: each lane owns 8
// consecutive floats (2x float4). Local serial scan (7 FMA) -> warp Kogge-Stone
// on the lane aggregate with ratio q^8 (5 shfl) -> recombine. Carry seeded by a
// warp-parallel 100-tap FIR. No smem, no block barriers.
// R12: launch_bounds(,6) kept (occ 63%), streaming stores REVERTED (cost 3.3us).

#define T_LEN   8192
#define KC_NUM  128
#define L_FIR   100
#define SEG     1024
#define TPB     256
#define WARPS_PER_BLOCK (TPB / 32)
#define VPT     8
#define MACRO   (32 * VPT)        // 256 elems per warp macro-step
#define STEPS   (SEG / MACRO)     // 4

__global__ __launch_bounds__(TPB, 6)
void per_band_soft_agc_kernel(const float* __restrict__ x,
                              const float* __restrict__ alpha_raw,
                              const float* __restrict__ log_s,
                              float* __restrict__ out)
{
    const unsigned FULL = 0xffffffffu;
    const int gw   = blockIdx.x * WARPS_PER_BLOCK + (threadIdx.x >> 5);
    const int lane = threadIdx.x & 31;
    const int row  = gw >> 3;                 // 8 segments per row
    const int o    = (gw & 7) * SEG;
    const int kc   = row & (KC_NUM - 1);

    const float* __restrict__ xr   = x   + (size_t)row * T_LEN;
    float*       __restrict__ orow = out + (size_t)row * T_LEN;

    // ---- per-channel scalars (warp-uniform) ----
    const float ls    = log_s[kc];
    const float s     = 1.0f / (1.0f + __expf(-ls));
    const float q     = 1.0f - s;
    const float l2q   = __log2f(q);
    const float qL    = exp2f(l2q * (float)L_FIR);          // q^100
    const float c     = s / ((1.0f - qL) + 1e-8f);
    const float ncqL  = -c * qL;
    const float ar    = alpha_raw[kc];
    const float alpha = 0.5f / (1.0f + __expf(-ar));

    // hoisted powers of q (all loop-invariant)
    float qp[VPT];                                           // q^1 .. q^8
    qp[0] = q;
    #pragma unroll
    for (int j = 1; j < VPT; ++j) qp[j] = qp[j - 1] * q;
    const float r1 = qp[VPT - 1];                            // q^8
    const float r2 = r1 * r1, r4 = r2 * r2, r8 = r4 * r4, r16 = r8 * r8;
    const float q256 = r16 * r16;                            // q^256
    const float q8l  = exp2f(l2q * (float)(VPT * lane));     // q^(8*lane)
    const float q32  = exp2f(l2q * 32.0f);
    const float qlane = exp2f(l2q * (float)lane);

    // ---- seed carry = M[o-1] via warp-parallel 100-tap FIR ----
    float carry = 0.0f;
    if (o > 0) {
        const float q64 = q32 * q32;
        const float q96 = q64 * q32;
        const int   b   = o - 1 - lane;
        float t = fabsf(xr[b]);
        t = fmaf(q32, fabsf(xr[b - 32]), t);
        t = fmaf(q64, fabsf(xr[b - 64]), t);
        if (lane < 4) t = fmaf(q96, fabsf(xr[b - 96]), t);
        t *= c * qlane;
        #pragma unroll
        for (int d = 16; d > 0; d >>= 1)
            t += __shfl_xor_sync(FULL, t, d);
        carry = t;                                           // exact M[o-1]
    }

    // ---- main loop: 4 macro-steps of 256 elements ----
    #pragma unroll 2
    for (int step = 0; step < STEPS; ++step) {
        const int pb = o + step * MACRO + lane * VPT;        // 8-aligned -> 16B aligned

        float xv[VPT];
        {   // two LDG.128, coalesced
            const float4 v0 = *(const float4*)(xr + pb);
            const float4 v1 = *(const float4*)(xr + pb + 4);
            xv[0] = v0.x; xv[1] = v0.y; xv[2] = v0.z; xv[3] = v0.w;
            xv[4] = v1.x; xv[5] = v1.y; xv[6] = v1.z; xv[7] = v1.w;
        }

        float xo[VPT];
        if (pb >= L_FIR) {                                   // (pb-100) % 4 == 0 -> aligned
            const float4 v0 = *(const float4*)(xr + pb - L_FIR);
            const float4 v1 = *(const float4*)(xr + pb - L_FIR + 4);
            xo[0] = v0.x; xo[1] = v0.y; xo[2] = v0.z; xo[3] = v0.w;
            xo[4] = v1.x; xo[5] = v1.y; xo[6] = v1.z; xo[7] = v1.w;
        } else {                                             // first segment, step 0 only
            #pragma unroll
            for (int j = 0; j < VPT; ++j) {
                const int p = pb + j;
                xo[j] = (p >= L_FIR) ? xr[p - L_FIR] : 0.0f;
            }
        }

        // u_j then local inclusive weighted scan (in place)
        float a[VPT];
        a[0] = fmaf(c, fabsf(xv[0]), ncqL * fabsf(xo[0]));
        #pragma unroll
        for (int j = 1; j < VPT; ++j) {
            const float u = fmaf(c, fabsf(xv[j]), ncqL * fabsf(xo[j]));
            a[j] = fmaf(q, a[j - 1], u);
        }

        // warp inclusive scan of lane aggregates with ratio q^8
        float S = a[VPT - 1];
        { float t = __shfl_up_sync(FULL, S, 1);  if (lane >= 1)  S = fmaf(r1,  t, S); }
        { float t = __shfl_up_sync(FULL, S, 2);  if (lane >= 2)  S = fmaf(r2,  t, S); }
        { float t = __shfl_up_sync(FULL, S, 4);  if (lane >= 4)  S = fmaf(r4,  t, S); }
        { float t = __shfl_up_sync(FULL, S, 8);  if (lane >= 8)  S = fmaf(r8,  t, S); }
        { float t = __shfl_up_sync(FULL, S, 16); if (lane >= 16) S = fmaf(r16, t, S); }

        // exclusive prefix from lanes below + incoming carry
        const float Ex = __shfl_up_sync(FULL, S, 1);
        const float E  = (lane >= 1) ? Ex : 0.0f;
        const float w  = fmaf(q8l, carry, E);

        const float S31 = __shfl_sync(FULL, S, 31);
        carry = fmaf(q256, carry, S31);                      // only serial cross-step dep

        // full M, gain, divide, store
        float4 r0, r1v;
        #pragma unroll
        for (int j = 0; j < VPT; ++j) {
            const float M  = fmaf(qp[j], w, a[j]);
            const float g  = __powf(fmaxf(M, 1e-6f), alpha) + 0.1f;
            const float rj = __fdividef(xv[j], g);
            if (j < 4) (&r0.x)[j] = rj; else (&r1v.x)[j - 4] = rj;
        }
        *(float4*)(orow + pb)     = r0;                      // STG.128, coalesced
        *(float4*)(orow + pb + 4) = r1v;
    }
}

extern "C" void kernel_launch(void* const* d_in, const int* in_sizes, int n_in,
                              void* d_out, int out_size)
{
    const float* x         = (const float*)d_in[0];
    const float* alpha_raw = (const float*)d_in[1];
    const float* log_s     = (const float*)d_in[2];
    float*       out       = (float*)d_out;

    const int rows   = in_sizes[0] / T_LEN;                 // 4096
    const int warps  = rows * (T_LEN / SEG);                // 32768
    const int blocks = warps / WARPS_PER_BLOCK;             // 4096
    per_band_soft_agc_kernel<<<blocks, TPB>>>(x, alpha_raw, log_s, out);
}

// round 16
// speedup vs baseline: 1.0907x; 1.0827x over previous
#include <cuda_runtime.h>

// PerBandSoftAGC: out = x / (clip(EMA100(|x|), 1e-6)^alpha + 0.1)
// x: (32, 8, 16, 8192) fp32 -> 4096 rows of T=8192, channel kc = row % 128.
// EMA weights w_i = c*q^i (i<100), q = 1 - sigmoid(log_s), c = s/((1-q^100)+1e-8).
// Linear recurrence M[t] = q*M[t-1] + u[t], u[t] = c|x[t]| - c*q^100*|x[t-100]|.
//
// One WARP per 1024-elem segment. R14: the whole segment's x (8x LDG.128 per
// lane-group, 4KB/warp) is PRELOADED front-batched for max MLP before the scan
// loop; lag reads then hit L1/L2 on just-fetched lines. Per 256-elem step:
// local serial scan (7 FMA) -> warp Kogge-Stone on lane aggregate, ratio q^8
// (5 shfl) -> recombine. Carry seeded by warp-parallel 100-tap FIR. No smem.

#define T_LEN   8192
#define KC_NUM  128
#define L_FIR   100
#define SEG     1024
#define TPB     256
#define WARPS_PER_BLOCK (TPB / 32)
#define VPT     8
#define MACRO   (32 * VPT)        // 256 elems per warp macro-step
#define STEPS   (SEG / MACRO)     // 4

__global__ __launch_bounds__(TPB)
void per_band_soft_agc_kernel(const float* __restrict__ x,
                              const float* __restrict__ alpha_raw,
                              const float* __restrict__ log_s,
                              float* __restrict__ out)
{
    const unsigned FULL = 0xffffffffu;
    const int gw   = blockIdx.x * WARPS_PER_BLOCK + (threadIdx.x >> 5);
    const int lane = threadIdx.x & 31;
    const int row  = gw >> 3;                 // 8 segments per row
    const int o    = (gw & 7) * SEG;
    const int kc   = row & (KC_NUM - 1);

    const float* __restrict__ xr   = x   + (size_t)row * T_LEN;
    float*       __restrict__ orow = out + (size_t)row * T_LEN;

    // ---- FRONT-BATCHED segment preload: 8 consecutive LDG.128 (max MLP) ----
    float4 vv[STEPS][2];
    #pragma unroll
    for (int st = 0; st < STEPS; ++st) {
        const float* p = xr + o + st * MACRO + lane * VPT;
        vv[st][0] = *(const float4*)p;
        vv[st][1] = *(const float4*)(p + 4);
    }

    // ---- per-channel scalars (warp-uniform; overlaps with loads in flight) ----
    const float ls    = log_s[kc];
    const float s     = 1.0f / (1.0f + __expf(-ls));
    const float q     = 1.0f - s;
    const float l2q   = __log2f(q);
    const float qL    = exp2f(l2q * (float)L_FIR);          // q^100
    const float c     = s / ((1.0f - qL) + 1e-8f);
    const float ncqL  = -c * qL;
    const float ar    = alpha_raw[kc];
    const float alpha = 0.5f / (1.0f + __expf(-ar));

    // hoisted powers of q (all loop-invariant)
    float qp[VPT];                                           // q^1 .. q^8
    qp[0] = q;
    #pragma unroll
    for (int j = 1; j < VPT; ++j) qp[j] = qp[j - 1] * q;
    const float r1 = qp[VPT - 1];                            // q^8
    const float r2 = r1 * r1, r4 = r2 * r2, r8 = r4 * r4, r16 = r8 * r8;
    const float q256 = r16 * r16;                            // q^256
    const float q8l  = exp2f(l2q * (float)(VPT * lane));     // q^(8*lane)
    const float q32  = exp2f(l2q * 32.0f);
    const float qlane = exp2f(l2q * (float)lane);

    // ---- seed carry = M[o-1] via warp-parallel 100-tap FIR (L2-hit reads) ----
    float carry = 0.0f;
    if (o > 0) {
        const float q64 = q32 * q32;
        const float q96 = q64 * q32;
        const int   b   = o - 1 - lane;
        float t = fabsf(xr[b]);
        t = fmaf(q32, fabsf(xr[b - 32]), t);
        t = fmaf(q64, fabsf(xr[b - 64]), t);
        if (lane < 4) t = fmaf(q96, fabsf(xr[b - 96]), t);
        t *= c * qlane;
        #pragma unroll
        for (int d = 16; d > 0; d >>= 1)
            t += __shfl_xor_sync(FULL, t, d);
        carry = t;                                           // exact M[o-1]
    }

    // ---- main loop: 4 macro-steps of 256 elements (fully unrolled) ----
    #pragma unroll
    for (int step = 0; step < STEPS; ++step) {
        const int pb = o + step * MACRO + lane * VPT;        // 16B aligned

        float xv[VPT];
        xv[0] = vv[step][0].x; xv[1] = vv[step][0].y;
        xv[2] = vv[step][0].z; xv[3] = vv[step][0].w;
        xv[4] = vv[step][1].x; xv[5] = vv[step][1].y;
        xv[6] = vv[step][1].z; xv[7] = vv[step][1].w;

        // lag reads: lines already fetched by the preload -> L1/L2 hits
        float xo[VPT];
        if (pb >= L_FIR) {                                   // (pb-100) % 4 == 0 -> aligned
            const float4 v0 = *(const float4*)(xr + pb - L_FIR);
            const float4 v1 = *(const float4*)(xr + pb - L_FIR + 4);
            xo[0] = v0.x; xo[1] = v0.y; xo[2] = v0.z; xo[3] = v0.w;
            xo[4] = v1.x; xo[5] = v1.y; xo[6] = v1.z; xo[7] = v1.w;
        } else {                                             // first segment, step 0 only
            #pragma unroll
            for (int j = 0; j < VPT; ++j) {
                const int p = pb + j;
                xo[j] = (p >= L_FIR) ? xr[p - L_FIR] : 0.0f;
            }
        }

        // u_j then local inclusive weighted scan (in place)
        float a[VPT];
        a[0] = fmaf(c, fabsf(xv[0]), ncqL * fabsf(xo[0]));
        #pragma unroll
        for (int j = 1; j < VPT; ++j) {
            const float u = fmaf(c, fabsf(xv[j]), ncqL * fabsf(xo[j]));
            a[j] = fmaf(q, a[j - 1], u);
        }

        // warp inclusive scan of lane aggregates with ratio q^8
        float S = a[VPT - 1];
        { float t = __shfl_up_sync(FULL, S, 1);  if (lane >= 1)  S = fmaf(r1,  t, S); }
        { float t = __shfl_up_sync(FULL, S, 2);  if (lane >= 2)  S = fmaf(r2,  t, S); }
        { float t = __shfl_up_sync(FULL, S, 4);  if (lane >= 4)  S = fmaf(r4,  t, S); }
        { float t = __shfl_up_sync(FULL, S, 8);  if (lane >= 8)  S = fmaf(r8,  t, S); }
        { float t = __shfl_up_sync(FULL, S, 16); if (lane >= 16) S = fmaf(r16, t, S); }

        // exclusive prefix from lanes below + incoming carry
        const float Ex = __shfl_up_sync(FULL, S, 1);
        const float E  = (lane >= 1) ? Ex : 0.0f;
        const float w  = fmaf(q8l, carry, E);

        const float S31 = __shfl_sync(FULL, S, 31);
        carry = fmaf(q256, carry, S31);                      // only serial cross-step dep

        // full M, gain, divide, store
        float4 r0, r1v;
        #pragma unroll
        for (int j = 0; j < VPT; ++j) {
            const float M  = fmaf(qp[j], w, a[j]);
            const float g  = __powf(fmaxf(M, 1e-6f), alpha) + 0.1f;
            const float rj = __fdividef(xv[j], g);
            if (j < 4) (&r0.x)[j] = rj; else (&r1v.x)[j - 4] = rj;
        }
        *(float4*)(orow + pb)     = r0;                      // STG.128, coalesced
        *(float4*)(orow + pb + 4) = r1v;
    }
}

extern "C" void kernel_launch(void* const* d_in, const int* in_sizes, int n_in,
                              void* d_out, int out_size)
{
    const float* x         = (const float*)d_in[0];
    const float* alpha_raw = (const float*)d_in[1];
    const float* log_s     = (const float*)d_in[2];
    float*       out       = (float*)d_out;

    const int rows   = in_sizes[0] / T_LEN;                 // 4096
    const int warps  = rows * (T_LEN / SEG);                // 32768
    const int blocks = warps / WARPS_PER_BLOCK;             // 4096
    per_band_soft_agc_kernel<<<blocks, TPB>>>(x, alpha_raw, log_s, out);
}

// round 17
// speedup vs baseline: 1.0915x; 1.0007x over previous
#include <cuda_runtime.h>

// PerBandSoftAGC: out = x / (clip(EMA100(|x|), 1e-6)^alpha + 0.1)
// x: (32, 8, 16, 8192) fp32 -> 4096 rows of T=8192, channel kc = row % 128.
// EMA weights w_i = c*q^i (i<100), q = 1 - sigmoid(log_s), c = s/((1-q^100)+1e-8).
// Linear recurrence M[t] = q*M[t-1] + u[t], u[t] = c|x[t]| - c*q^100*|x[t-100]|.
//
// One WARP per 1024-elem segment. Whole segment's x (8x LDG.128/lane) is
// PRELOADED front-batched for max MLP; lag reads hit L1 on just-fetched lines.
// Per 256-elem step: local serial scan (7 FMA) -> warp Kogge-Stone on lane
// aggregate, ratio q^8 (5 shfl) -> recombine. Carry seeded by warp-parallel
// 100-tap FIR. No smem.
// R17: __launch_bounds__(TPB, 4) -> 64-reg cap, 4 CTAs/SM (occ 32->42%),
//      preload kept intact (needs only 32 live payload regs).

#define T_LEN   8192
#define KC_NUM  128
#define L_FIR   100
#define SEG     1024
#define TPB     256
#define WARPS_PER_BLOCK (TPB / 32)
#define VPT     8
#define MACRO   (32 * VPT)        // 256 elems per warp macro-step
#define STEPS   (SEG / MACRO)     // 4

__global__ __launch_bounds__(TPB, 4)
void per_band_soft_agc_kernel(const float* __restrict__ x,
                              const float* __restrict__ alpha_raw,
                              const float* __restrict__ log_s,
                              float* __restrict__ out)
{
    const unsigned FULL = 0xffffffffu;
    const int gw   = blockIdx.x * WARPS_PER_BLOCK + (threadIdx.x >> 5);
    const int lane = threadIdx.x & 31;
    const int row  = gw >> 3;                 // 8 segments per row
    const int o    = (gw & 7) * SEG;
    const int kc   = row & (KC_NUM - 1);

    const float* __restrict__ xr   = x   + (size_t)row * T_LEN;
    float*       __restrict__ orow = out + (size_t)row * T_LEN;

    // ---- FRONT-BATCHED segment preload: 8 consecutive LDG.128 (max MLP) ----
    float4 vv[STEPS][2];
    #pragma unroll
    for (int st = 0; st < STEPS; ++st) {
        const float* p = xr + o + st * MACRO + lane * VPT;
        vv[st][0] = *(const float4*)p;
        vv[st][1] = *(const float4*)(p + 4);
    }

    // ---- per-channel scalars (warp-uniform; overlaps with loads in flight) ----
    const float ls    = log_s[kc];
    const float s     = 1.0f / (1.0f + __expf(-ls));
    const float q     = 1.0f - s;
    const float l2q   = __log2f(q);
    const float qL    = exp2f(l2q * (float)L_FIR);          // q^100
    const float c     = s / ((1.0f - qL) + 1e-8f);
    const float ncqL  = -c * qL;
    const float ar    = alpha_raw[kc];
    const float alpha = 0.5f / (1.0f + __expf(-ar));

    // hoisted powers of q (all loop-invariant)
    float qp[VPT];                                           // q^1 .. q^8
    qp[0] = q;
    #pragma unroll
    for (int j = 1; j < VPT; ++j) qp[j] = qp[j - 1] * q;
    const float r1 = qp[VPT - 1];                            // q^8
    const float r2 = r1 * r1, r4 = r2 * r2, r8 = r4 * r4, r16 = r8 * r8;
    const float q256 = r16 * r16;                            // q^256
    const float q8l  = exp2f(l2q * (float)(VPT * lane));     // q^(8*lane)
    const float q32  = exp2f(l2q * 32.0f);
    const float qlane = exp2f(l2q * (float)lane);

    // ---- seed carry = M[o-1] via warp-parallel 100-tap FIR (L2-hit reads) ----
    float carry = 0.0f;
    if (o > 0) {
        const float q64 = q32 * q32;
        const float q96 = q64 * q32;
        const int   b   = o - 1 - lane;
        float t = fabsf(xr[b]);
        t = fmaf(q32, fabsf(xr[b - 32]), t);
        t = fmaf(q64, fabsf(xr[b - 64]), t);
        if (lane < 4) t = fmaf(q96, fabsf(xr[b - 96]), t);
        t *= c * qlane;
        #pragma unroll
        for (int d = 16; d > 0; d >>= 1)
            t += __shfl_xor_sync(FULL, t, d);
        carry = t;                                           // exact M[o-1]
    }

    // ---- main loop: 4 macro-steps of 256 elements (fully unrolled) ----
    #pragma unroll
    for (int step = 0; step < STEPS; ++step) {
        const int pb = o + step * MACRO + lane * VPT;        // 16B aligned

        float xv[VPT];
        xv[0] = vv[step][0].x; xv[1] = vv[step][0].y;
        xv[2] = vv[step][0].z; xv[3] = vv[step][0].w;
        xv[4] = vv[step][1].x; xv[5] = vv[step][1].y;
        xv[6] = vv[step][1].z; xv[7] = vv[step][1].w;

        // lag reads: lines already fetched by the preload -> L1/L2 hits
        float xo[VPT];
        if (pb >= L_FIR) {                                   // (pb-100) % 4 == 0 -> aligned
            const float4 v0 = *(const float4*)(xr + pb - L_FIR);
            const float4 v1 = *(const float4*)(xr + pb - L_FIR + 4);
            xo[0] = v0.x; xo[1] = v0.y; xo[2] = v0.z; xo[3] = v0.w;
            xo[4] = v1.x; xo[5] = v1.y; xo[6] = v1.z; xo[7] = v1.w;
        } else {                                             // first segment, step 0 only
            #pragma unroll
            for (int j = 0; j < VPT; ++j) {
                const int p = pb + j;
                xo[j] = (p >= L_FIR) ? xr[p - L_FIR] : 0.0f;
            }
        }

        // u_j then local inclusive weighted scan (in place)
        float a[VPT];
        a[0] = fmaf(c, fabsf(xv[0]), ncqL * fabsf(xo[0]));
        #pragma unroll
        for (int j = 1; j < VPT; ++j) {
            const float u = fmaf(c, fabsf(xv[j]), ncqL * fabsf(xo[j]));
            a[j] = fmaf(q, a[j - 1], u);
        }

        // warp inclusive scan of lane aggregates with ratio q^8
        float S = a[VPT - 1];
        { float t = __shfl_up_sync(FULL, S, 1);  if (lane >= 1)  S = fmaf(r1,  t, S); }
        { float t = __shfl_up_sync(FULL, S, 2);  if (lane >= 2)  S = fmaf(r2,  t, S); }
        { float t = __shfl_up_sync(FULL, S, 4);  if (lane >= 4)  S = fmaf(r4,  t, S); }
        { float t = __shfl_up_sync(FULL, S, 8);  if (lane >= 8)  S = fmaf(r8,  t, S); }
        { float t = __shfl_up_sync(FULL, S, 16); if (lane >= 16) S = fmaf(r16, t, S); }

        // exclusive prefix from lanes below + incoming carry
        const float Ex = __shfl_up_sync(FULL, S, 1);
        const float E  = (lane >= 1) ? Ex : 0.0f;
        const float w  = fmaf(q8l, carry, E);

        const float S31 = __shfl_sync(FULL, S, 31);
        carry = fmaf(q256, carry, S31);                      // only serial cross-step dep

        // full M, gain, divide, store
        float4 r0, r1v;
        #pragma unroll
        for (int j = 0; j < VPT; ++j) {
            const float M  = fmaf(qp[j], w, a[j]);
            const float g  = __powf(fmaxf(M, 1e-6f), alpha) + 0.1f;
            const float rj = __fdividef(xv[j], g);
            if (j < 4) (&r0.x)[j] = rj; else (&r1v.x)[j - 4] = rj;
        }
        *(float4*)(orow + pb)     = r0;                      // STG.128, coalesced
        *(float4*)(orow + pb + 4) = r1v;
    }
}

extern "C" void kernel_launch(void* const* d_in, const int* in_sizes, int n_in,
                              void* d_out, int out_size)
{
    const float* x         = (const float*)d_in[0];
    const float* alpha_raw = (const float*)d_in[1];
    const float* log_s     = (const float*)d_in[2];
    float*       out       = (float*)d_out;

    const int rows   = in_sizes[0] / T_LEN;                 // 4096
    const int warps  = rows * (T_LEN / SEG);                // 32768
    const int blocks = warps / WARPS_PER_BLOCK;             // 4096
    per_band_soft_agc_kernel<<<blocks, TPB>>>(x, alpha_raw, log_s, out);
}